// round 1
// baseline (speedup 1.0000x reference)
#include <cuda_runtime.h>

// SSKernelDiag: out[h,l] = 2 * Re( sum_n Cc[h,n] * A[h,n]^l )
//   A  = exp(abslog + i*phase), dtA = abslog + i*phase
//   Cc = C * (A - 1) / dtA
// H=256, N=64, L=4096, CH=1.
//
// Strategy: per (h, chunk-of-1024-l) block.
//   A^(l0 + 64*tile + t) = P(l0,tile) * q(t),  q(t)=A^t cached in REGISTERS
//   (thread owns one t in [0,64) and half of the n's -> 32 complex q in regs).
//   W[tile][n] = 2*Cc*P precomputed into smem (16-step recurrence from an
//   exact Cody-Waite anchor). Inner loop = 1 broadcast LDS.64 + 2 FFMA / term.

#define HH 256
#define NN 64
#define LL 4096
#define CHUNKS 4
#define LCHUNK 1024
#define TILE 64
#define NTILES 16
#define NTHREADS 128
#define NHALF 32

__device__ __forceinline__ float2 cmul(float2 a, float2 b) {
    return make_float2(fmaf(a.x, b.x, -(a.y * b.y)),
                       fmaf(a.x, b.y,  (a.y * b.x)));
}

// exp(i*y) with 2-term Cody-Waite range reduction; good for |y| up to ~1e4.
__device__ __forceinline__ float2 cis_cw(float y) {
    float m = rintf(y * 0.15915494309189535f);      // y / (2*pi)
    float r = fmaf(m, -6.28125f, y);                // 2*pi hi (exact fp32)
    r = fmaf(m, -1.9353072e-3f, r);                 // 2*pi lo
    float s, c;
    __sincosf(r, &s, &c);
    return make_float2(c, s);
}

__global__ void __launch_bounds__(NTHREADS, 4)
ssk_diag_kernel(const float* __restrict__ abslog,
                const float* __restrict__ phase,
                const float* __restrict__ C,
                float* __restrict__ out) {
    __shared__ float2 sW[NTILES][NN];          // 8 KB: W per tile per n
    __shared__ float2 sQ[NN * TILE];           // 32 KB: q table (transient)
    float* sP = reinterpret_cast<float*>(sQ);  // aliased: partial[2][LCHUNK]

    const int bid   = blockIdx.x;
    const int h     = bid >> 2;        // / CHUNKS
    const int chunk = bid & (CHUNKS - 1);
    const int tid   = threadIdx.x;
    const int t     = tid & (TILE - 1);
    const int g     = tid >> 6;        // n-half: 0 or 1

    const float l0f = (float)(chunk * LCHUNK);
    const float* alh = abslog + h * NN;
    const float* phh = phase  + h * NN;

    // ---- W table: threads 0..63, one n each ----
    if (tid < NN) {
        const int n = tid;
        const float al = alh[n];
        const float ph = phh[n];

        float er = __expf(al);
        float s0, c0;
        __sincosf(ph, &s0, &c0);                 // |ph| <= pi
        float2 A   = make_float2(er * c0, er * s0);
        float2 Am1 = make_float2(A.x - 1.0f, A.y);

        float2 Cin = make_float2(C[(h * NN + n) * 2],
                                 C[(h * NN + n) * 2 + 1]);
        float2 num = cmul(Cin, Am1);
        float  inv = 1.0f / fmaf(al, al, ph * ph);   // |dtA|^2
        float2 Cc;                                   // 2 * num / dtA
        Cc.x = 2.0f * (num.x * al + num.y * ph) * inv;
        Cc.y = 2.0f * (num.y * al - num.x * ph) * inv;

        // P = A^(l0) via exact anchor
        float2 P  = cis_cw(ph * l0f);
        float  E0 = __expf(al * l0f);
        P.x *= E0; P.y *= E0;

        // A^64
        float2 A64 = cis_cw(ph * 64.0f);
        float  E64 = __expf(al * 64.0f);
        A64.x *= E64; A64.y *= E64;

        #pragma unroll
        for (int tl = 0; tl < NTILES; tl++) {
            sW[tl][n] = cmul(Cc, P);
            P = cmul(P, A64);
        }
    }

    // ---- q table: q[n][t] = A_n^t, t in [0,64) ----
    for (int idx = tid; idx < NN * TILE; idx += NTHREADS) {
        const int   n  = idx >> 6;
        const int   tt = idx & (TILE - 1);
        const float al = alh[n];
        const float ph = phh[n];
        const float tf = (float)tt;
        float2 cs = cis_cw(ph * tf);
        float  e  = __expf(al * tf);
        sQ[idx] = make_float2(e * cs.x, e * cs.y);
    }
    __syncthreads();

    // ---- cache this thread's q column into registers ----
    float qr[NHALF], qn[NHALF];
    #pragma unroll
    for (int i = 0; i < NHALF; i++) {
        float2 v = sQ[(g * NHALF + i) * TILE + t];
        qr[i] =  v.x;
        qn[i] = -v.y;
    }
    __syncthreads();   // after this, sQ is dead; sP aliases it

    // ---- main loop: 16 tiles x 32 n x (1 LDS.64 + 2 FFMA) ----
    for (int tl = 0; tl < NTILES; tl++) {
        const float2* w = &sW[tl][g * NHALF];
        float a0 = 0.f, a1 = 0.f, a2 = 0.f, a3 = 0.f;
        #pragma unroll
        for (int i = 0; i < NHALF; i += 4) {
            float2 w0 = w[i], w1 = w[i + 1], w2 = w[i + 2], w3 = w[i + 3];
            a0 = fmaf(w0.x, qr[i],     a0); a0 = fmaf(w0.y, qn[i],     a0);
            a1 = fmaf(w1.x, qr[i + 1], a1); a1 = fmaf(w1.y, qn[i + 1], a1);
            a2 = fmaf(w2.x, qr[i + 2], a2); a2 = fmaf(w2.y, qn[i + 2], a2);
            a3 = fmaf(w3.x, qr[i + 3], a3); a3 = fmaf(w3.y, qn[i + 3], a3);
        }
        sP[g * LCHUNK + tl * TILE + t] = (a0 + a1) + (a2 + a3);
    }
    __syncthreads();

    // ---- reduce the two n-halves, write coalesced ----
    float* outh = out + h * LL + chunk * LCHUNK;
    for (int j = tid; j < LCHUNK; j += NTHREADS) {
        outh[j] = sP[j] + sP[LCHUNK + j];
    }
}

extern "C" void kernel_launch(void* const* d_in, const int* in_sizes, int n_in,
                              void* d_out, int out_size) {
    const float* abslog = (const float*)d_in[0];  // (H, N) f32
    const float* phase  = (const float*)d_in[1];  // (H, N) f32
    const float* C      = (const float*)d_in[2];  // (1, H, N, 2) f32
    // d_in[3] = L (constant 4096), unused
    float* out = (float*)d_out;                   // (1, H, L) f32

    ssk_diag_kernel<<<HH * CHUNKS, NTHREADS>>>(abslog, phase, C, out);
}

// round 2
// speedup vs baseline: 1.2452x; 1.2452x over previous
#include <cuda_runtime.h>

// SSKernelDiag: out[h,l] = 2 * Re( sum_n Cc[h,n] * A[h,n]^l )
//   A = exp(abslog + i*phase), dtA = abslog + i*phase, Cc = C*(A-1)/dtA
// H=256, N=64, L=4096, CH=1.
//
// R2: FFMA2 (fma.rn.f32x2) inner loop, LDS.128 W loads, 7 blocks/SM single wave.
//   l = chunk*1024 + 32*tl + t ;  A^l = W-recurrence(tl) * q(t), q in regs.
//   Thread (t in [0,32), g in [0,4)) owns 16 n: per tile 8 LDS.128 + 16 FFMA2.

#define HH 256
#define NN 64
#define LL 4096
#define CHUNKS 4
#define LCHUNK 1024
#define TILE 32
#define NTILES 32
#define NTHREADS 128
#define NQ 16            // n per group
#define NGROUPS 4

typedef unsigned long long ull;

__device__ __forceinline__ float2 cmul(float2 a, float2 b) {
    return make_float2(fmaf(a.x, b.x, -(a.y * b.y)),
                       fmaf(a.x, b.y,  (a.y * b.x)));
}

// exp(i*y), 2-term Cody-Waite reduction; exact for |y| <~ 2^14.
__device__ __forceinline__ float2 cis_cw(float y) {
    float m = rintf(y * 0.15915494309189535f);
    float r = fmaf(m, -6.28125f, y);          // 2*pi hi (exact in fp32)
    r = fmaf(m, -1.9353072e-3f, r);           // 2*pi lo
    float s, c;
    __sincosf(r, &s, &c);
    return make_float2(c, s);
}

__device__ __forceinline__ ull pack2(float x, float y) {
    ull r;
    asm("mov.b64 %0, {%1, %2};" : "=l"(r) : "f"(x), "f"(y));
    return r;
}
__device__ __forceinline__ float2 unpack2(ull v) {
    float x, y;
    asm("mov.b64 {%0, %1}, %2;" : "=f"(x), "=f"(y) : "l"(v));
    return make_float2(x, y);
}
__device__ __forceinline__ void ffma2(ull& acc, ull a, ull b) {
    asm("fma.rn.f32x2 %0, %1, %2, %0;" : "+l"(acc) : "l"(a), "l"(b));
}
__device__ __forceinline__ ull fadd2(ull a, ull b) {
    ull r;
    asm("add.rn.f32x2 %0, %1, %2;" : "=l"(r) : "l"(a), "l"(b));
    return r;
}

__global__ void __launch_bounds__(NTHREADS, 7)
ssk_diag_kernel(const float* __restrict__ abslog,
                const float* __restrict__ phase,
                const float* __restrict__ C,
                float* __restrict__ out) {
    __shared__ float2 sW[NTILES][NN];     // 16 KB: W[tl][n] = 2*Cc*A^(l0+32*tl)
    __shared__ float  uni[NGROUPS * LCHUNK];  // 16 KB: qtab (prologue) / sP (main)
    float2* qtab = reinterpret_cast<float2*>(uni);  // [n][12]: 8 qlo + 4 qhi
    float*  sP   = uni;

    const int bid   = blockIdx.x;
    const int h     = bid >> 2;
    const int chunk = bid & (CHUNKS - 1);
    const int tid   = threadIdx.x;
    const int t     = tid & (TILE - 1);
    const int g     = tid >> 5;

    const float* alh = abslog + h * NN;
    const float* phh = phase  + h * NN;
    const float  l0f = (float)(chunk * LCHUNK);

    // ---- phase A: q factor tables: qtab[n][j] = A^j (j<8), A^(8*(j-8)) (j>=8) ----
    #pragma unroll
    for (int k = 0; k < 6; k++) {
        const int e = tid + k * NTHREADS;     // 768 entries
        const int n = e / 12;
        const int j = e % 12;
        const float f  = (j < 8) ? (float)j : (float)(8 * (j - 8));
        const float al = alh[n];
        const float ph = phh[n];
        float2 cs = cis_cw(ph * f);
        float  ex = __expf(al * f);
        qtab[n * 12 + j] = make_float2(ex * cs.x, ex * cs.y);
    }

    // ---- phase B: W table, 2 halves of 16-tile recurrences per n ----
    {
        const int n    = tid & (NN - 1);
        const int half = tid >> 6;
        const float al = alh[n];
        const float ph = phh[n];

        float er = __expf(al);
        float s0, c0;
        __sincosf(ph, &s0, &c0);
        float2 A   = make_float2(er * c0, er * s0);
        float2 Am1 = make_float2(A.x - 1.0f, A.y);
        float2 Cin = make_float2(C[(h * NN + n) * 2], C[(h * NN + n) * 2 + 1]);
        float2 num = cmul(Cin, Am1);
        float  inv = 1.0f / fmaf(al, al, ph * ph);
        float2 Cc;
        Cc.x = 2.0f * (num.x * al + num.y * ph) * inv;
        Cc.y = 2.0f * (num.y * al - num.x * ph) * inv;

        const float e0 = l0f + 512.0f * (float)half;   // anchor exponent
        float2 P  = cis_cw(ph * e0);
        float  E0 = __expf(al * e0);
        P.x *= E0; P.y *= E0;
        float2 A32 = cis_cw(ph * 32.0f);
        float  E32 = __expf(al * 32.0f);
        A32.x *= E32; A32.y *= E32;

        #pragma unroll
        for (int s = 0; s < 16; s++) {
            sW[16 * half + s][n] = cmul(Cc, P);
            P = cmul(P, A32);
        }
    }
    __syncthreads();

    // ---- phase C: build register q: q[n][t] = qhi[n][t>>3] * qlo[n][t&7] ----
    ull qp[NQ];
    {
        const int jlo = t & 7;
        const int jhi = 8 + (t >> 3);
        #pragma unroll
        for (int i = 0; i < NQ; i++) {
            const int n = g * NQ + i;
            float2 lo = qtab[n * 12 + jlo];
            float2 hi = qtab[n * 12 + jhi];
            float2 q  = cmul(hi, lo);
            qp[i] = pack2(q.x, -q.y);    // (re, -im): Re(w*q) via elementwise FMA
        }
    }
    __syncthreads();   // qtab dead; sP aliases it

    // ---- main loop: 32 tiles x (8 LDS.128 + 16 FFMA2) ----
    const ull zero = pack2(0.0f, 0.0f);
    for (int tl = 0; tl < NTILES; tl++) {
        const ulonglong2* w =
            reinterpret_cast<const ulonglong2*>(&sW[tl][g * NQ]);
        ull a0 = zero, a1 = zero, a2 = zero, a3 = zero;
        #pragma unroll
        for (int i = 0; i < 8; i += 2) {
            ulonglong2 w0 = w[i];
            ulonglong2 w1 = w[i + 1];
            ffma2(a0, w0.x, qp[2 * i]);
            ffma2(a1, w0.y, qp[2 * i + 1]);
            ffma2(a2, w1.x, qp[2 * i + 2]);
            ffma2(a3, w1.y, qp[2 * i + 3]);
        }
        ull s = fadd2(fadd2(a0, a1), fadd2(a2, a3));
        float2 u = unpack2(s);
        sP[g * LCHUNK + tl * TILE + t] = u.x + u.y;
    }
    __syncthreads();

    // ---- epilogue: reduce 4 n-groups, coalesced store ----
    float* outh = out + h * LL + chunk * LCHUNK;
    for (int j = tid; j < LCHUNK; j += NTHREADS) {
        outh[j] = (sP[j] + sP[LCHUNK + j]) +
                  (sP[2 * LCHUNK + j] + sP[3 * LCHUNK + j]);
    }
}

extern "C" void kernel_launch(void* const* d_in, const int* in_sizes, int n_in,
                              void* d_out, int out_size) {
    const float* abslog = (const float*)d_in[0];  // (H, N) f32
    const float* phase  = (const float*)d_in[1];  // (H, N) f32
    const float* C      = (const float*)d_in[2];  // (1, H, N, 2) f32
    float* out = (float*)d_out;                   // (1, H, L) f32

    ssk_diag_kernel<<<HH * CHUNKS, NTHREADS>>>(abslog, phase, C, out);
}

// round 3
// speedup vs baseline: 1.2669x; 1.0174x over previous
#include <cuda_runtime.h>

// SSKernelDiag: out[h,l] = 2 * Re( sum_n Cc[h,n] * A[h,n]^l )
//   A = exp(abslog + i*phase), dtA = abslog + i*phase, Cc = C*(A-1)/dtA
// H=256, N=64, L=4096, CH=1.
//
// R3: each W load feeds TWO l-points (t, t+32). Thread (t in [0,32), g in
// [0,8)) owns 8 n; per 64-l tile: 4 LDS.128 + 16 FFMA2. q(t) and
// q(t+32)=q(t)*A^32 cached packed in registers. 256 thr/block, 3 blocks/SM.

#define HH 256
#define NN 64
#define CHUNKS 4
#define LCHUNK 1024
#define LL 4096
#define NTILES 16        // tiles of 64 l
#define NTHREADS 256
#define NQ 8             // n per group
#define NGROUPS 8
#define QSTRIDE 16       // qtab row stride (float2)

typedef unsigned long long ull;

__device__ __forceinline__ float2 cmul(float2 a, float2 b) {
    return make_float2(fmaf(a.x, b.x, -(a.y * b.y)),
                       fmaf(a.x, b.y,  (a.y * b.x)));
}

// exp(i*y), 2-term Cody-Waite reduction; exact for |y| <~ 2^14.
__device__ __forceinline__ float2 cis_cw(float y) {
    float m = rintf(y * 0.15915494309189535f);
    float r = fmaf(m, -6.28125f, y);          // 2*pi hi (exact in fp32)
    r = fmaf(m, -1.9353072e-3f, r);           // 2*pi lo
    float s, c;
    __sincosf(r, &s, &c);
    return make_float2(c, s);
}

__device__ __forceinline__ ull pack2(float x, float y) {
    ull r;
    asm("mov.b64 %0, {%1, %2};" : "=l"(r) : "f"(x), "f"(y));
    return r;
}
__device__ __forceinline__ float2 unpack2(ull v) {
    float x, y;
    asm("mov.b64 {%0, %1}, %2;" : "=f"(x), "=f"(y) : "l"(v));
    return make_float2(x, y);
}
__device__ __forceinline__ void ffma2(ull& acc, ull a, ull b) {
    asm("fma.rn.f32x2 %0, %1, %2, %0;" : "+l"(acc) : "l"(a), "l"(b));
}
__device__ __forceinline__ ull fadd2(ull a, ull b) {
    ull r;
    asm("add.rn.f32x2 %0, %1, %2;" : "=l"(r) : "l"(a), "l"(b));
    return r;
}

__global__ void __launch_bounds__(NTHREADS, 3)
ssk_diag_kernel(const float* __restrict__ abslog,
                const float* __restrict__ phase,
                const float* __restrict__ C,
                float* __restrict__ out) {
    __shared__ float2 sW[NTILES][NN];              // 8 KB: W[tl][n], step A^64
    __shared__ float  pool[NGROUPS * LCHUNK];      // 32 KB: qtab / sP
    float2* qtab = reinterpret_cast<float2*>(pool);  // [64][16]
    float*  sP   = pool;

    const int bid   = blockIdx.x;
    const int h     = bid >> 2;
    const int chunk = bid & (CHUNKS - 1);
    const int tid   = threadIdx.x;
    const int t     = tid & 31;
    const int g     = tid >> 5;

    const float* alh = abslog + h * NN;
    const float* phh = phase  + h * NN;
    const float  l0f = (float)(chunk * LCHUNK);

    // ---- phase A: qtab[n][j] = A^f, f = j (j<8) | 8*(j-8) (8<=j<12) | 32 (j=12)
    #pragma unroll
    for (int k = 0; k < 4; k++) {
        const int e = tid + k * NTHREADS;         // 1024 slots, 64 n x 16
        const int n = e >> 4;
        const int j = e & 15;
        if (j < 13) {
            const float f  = (j < 8) ? (float)j
                           : (j < 12) ? (float)(8 * (j - 8)) : 32.0f;
            const float al = alh[n];
            const float ph = phh[n];
            float2 cs = cis_cw(ph * f);
            float  ex = __expf(al * f);
            qtab[n * QSTRIDE + j] = make_float2(ex * cs.x, ex * cs.y);
        }
    }

    // ---- phase B: W table; 4 anchors per n, recurrence depth 4 ----
    {
        const int n = tid & (NN - 1);
        const int q4 = tid >> 6;                  // quarter in [0,4)
        const float al = alh[n];
        const float ph = phh[n];

        float er = __expf(al);
        float s0, c0;
        __sincosf(ph, &s0, &c0);
        float2 A   = make_float2(er * c0, er * s0);
        float2 Am1 = make_float2(A.x - 1.0f, A.y);
        float2 Cin = make_float2(C[(h * NN + n) * 2], C[(h * NN + n) * 2 + 1]);
        float2 num = cmul(Cin, Am1);
        float  inv = 1.0f / fmaf(al, al, ph * ph);
        float2 Cc;
        Cc.x = 2.0f * (num.x * al + num.y * ph) * inv;
        Cc.y = 2.0f * (num.y * al - num.x * ph) * inv;

        const float e0 = l0f + 256.0f * (float)q4;
        float2 P  = cis_cw(ph * e0);
        float  E0 = __expf(al * e0);
        P.x *= E0; P.y *= E0;
        float2 A64 = cis_cw(ph * 64.0f);
        float  E64 = __expf(al * 64.0f);
        A64.x *= E64; A64.y *= E64;

        #pragma unroll
        for (int s = 0; s < 4; s++) {
            sW[4 * q4 + s][n] = cmul(Cc, P);
            P = cmul(P, A64);
        }
    }
    __syncthreads();

    // ---- phase C: register q: q(t) = qhi*qlo ; q(t+32) = q(t)*A^32 ----
    ull qp[NQ], qq[NQ];
    {
        const int jlo = t & 7;
        const int jhi = 8 + (t >> 3);
        #pragma unroll
        for (int i = 0; i < NQ; i++) {
            const int n = g * NQ + i;
            float2 lo  = qtab[n * QSTRIDE + jlo];
            float2 hi  = qtab[n * QSTRIDE + jhi];
            float2 a32 = qtab[n * QSTRIDE + 12];
            float2 q   = cmul(hi, lo);
            float2 q2  = cmul(q, a32);
            qp[i] = pack2(q.x,  -q.y);
            qq[i] = pack2(q2.x, -q2.y);
        }
    }
    __syncthreads();   // qtab dead; sP aliases it

    // ---- main loop: 16 tiles x (4 LDS.128 + 16 FFMA2 + 2 stores) ----
    const ull zero = pack2(0.0f, 0.0f);
    float* sPg = sP + g * LCHUNK + t;
    #pragma unroll 4
    for (int tl = 0; tl < NTILES; tl++) {
        const ulonglong2* w =
            reinterpret_cast<const ulonglong2*>(&sW[tl][g * NQ]);
        ulonglong2 w0 = w[0], w1 = w[1], w2 = w[2], w3 = w[3];
        ull a0 = zero, a1 = zero, b0 = zero, b1 = zero;
        ffma2(a0, w0.x, qp[0]); ffma2(b0, w0.x, qq[0]);
        ffma2(a1, w0.y, qp[1]); ffma2(b1, w0.y, qq[1]);
        ffma2(a0, w1.x, qp[2]); ffma2(b0, w1.x, qq[2]);
        ffma2(a1, w1.y, qp[3]); ffma2(b1, w1.y, qq[3]);
        ffma2(a0, w2.x, qp[4]); ffma2(b0, w2.x, qq[4]);
        ffma2(a1, w2.y, qp[5]); ffma2(b1, w2.y, qq[5]);
        ffma2(a0, w3.x, qp[6]); ffma2(b0, w3.x, qq[6]);
        ffma2(a1, w3.y, qp[7]); ffma2(b1, w3.y, qq[7]);
        float2 u0 = unpack2(fadd2(a0, a1));
        float2 u1 = unpack2(fadd2(b0, b1));
        sPg[tl * 64]      = u0.x + u0.y;
        sPg[tl * 64 + 32] = u1.x + u1.y;
    }
    __syncthreads();

    // ---- epilogue: reduce 8 groups with float4, coalesced store ----
    {
        const int j4 = tid * 4;
        float4 acc = *reinterpret_cast<const float4*>(&sP[j4]);
        #pragma unroll
        for (int gg = 1; gg < NGROUPS; gg++) {
            float4 v = *reinterpret_cast<const float4*>(&sP[gg * LCHUNK + j4]);
            acc.x += v.x; acc.y += v.y; acc.z += v.z; acc.w += v.w;
        }
        float* outh = out + h * LL + chunk * LCHUNK;
        *reinterpret_cast<float4*>(&outh[j4]) = acc;
    }
}

extern "C" void kernel_launch(void* const* d_in, const int* in_sizes, int n_in,
                              void* d_out, int out_size) {
    const float* abslog = (const float*)d_in[0];  // (H, N) f32
    const float* phase  = (const float*)d_in[1];  // (H, N) f32
    const float* C      = (const float*)d_in[2];  // (1, H, N, 2) f32
    float* out = (float*)d_out;                   // (1, H, L) f32

    ssk_diag_kernel<<<HH * CHUNKS, NTHREADS>>>(abslog, phase, C, out);
}

// round 4
// speedup vs baseline: 1.2768x; 1.0078x over previous
#include <cuda_runtime.h>

// SSKernelDiag: out[h,l] = 2 * Re( sum_n Cc[h,n] * A[h,n]^l )
//   A = exp(abslog + i*phase), dtA = abslog + i*phase, Cc = C*(A-1)/dtA
// H=256, N=64, L=4096, CH=1.
//
// R4: ONE block per head (grid=256, single wave at 2 blocks/SM) so the
// transcendental prologue runs once per 4096 l instead of once per 1024.
// Main loop: 64 tiles of 64 l; per tile 4 LDS.128 (broadcast) + 16 FFMA2;
// q(t), q(t+32)=q(t)*A^32 packed in registers. Output staged through smem
// in 8 sections of 512 l (static smem = 32KB sW + 16KB pool = 48KB).

#define HH 256
#define NN 64
#define LL 4096
#define NTILES 64          // tiles of 64 l
#define SECTIONS 8
#define TPS 8              // tiles per section
#define LSEC 512
#define NTHREADS 256
#define NQ 8               // n per group
#define NGROUPS 8
#define QSTRIDE 16         // qtab row stride (float2)

typedef unsigned long long ull;

__device__ __forceinline__ float2 cmul(float2 a, float2 b) {
    return make_float2(fmaf(a.x, b.x, -(a.y * b.y)),
                       fmaf(a.x, b.y,  (a.y * b.x)));
}

// exp(i*y), 2-term Cody-Waite reduction; exact enough for |y| <~ 2^14.
__device__ __forceinline__ float2 cis_cw(float y) {
    float m = rintf(y * 0.15915494309189535f);
    float r = fmaf(m, -6.28125f, y);          // 2*pi hi (exact in fp32)
    r = fmaf(m, -1.9353072e-3f, r);           // 2*pi lo
    float s, c;
    __sincosf(r, &s, &c);
    return make_float2(c, s);
}

__device__ __forceinline__ ull pack2(float x, float y) {
    ull r;
    asm("mov.b64 %0, {%1, %2};" : "=l"(r) : "f"(x), "f"(y));
    return r;
}
__device__ __forceinline__ float2 unpack2(ull v) {
    float x, y;
    asm("mov.b64 {%0, %1}, %2;" : "=f"(x), "=f"(y) : "l"(v));
    return make_float2(x, y);
}
__device__ __forceinline__ void ffma2(ull& acc, ull a, ull b) {
    asm("fma.rn.f32x2 %0, %1, %2, %0;" : "+l"(acc) : "l"(a), "l"(b));
}
__device__ __forceinline__ ull fadd2(ull a, ull b) {
    ull r;
    asm("add.rn.f32x2 %0, %1, %2;" : "=l"(r) : "l"(a), "l"(b));
    return r;
}

__global__ void __launch_bounds__(NTHREADS, 2)
ssk_diag_kernel(const float* __restrict__ abslog,
                const float* __restrict__ phase,
                const float* __restrict__ C,
                float* __restrict__ out) {
    __shared__ float2 sW[NTILES][NN];            // 32 KB: W[tl][n], step A^64
    __shared__ float  pool[NGROUPS * LSEC];      // 16 KB: qtab / sP
    float2* qtab = reinterpret_cast<float2*>(pool);  // [64][16] (8 KB used)
    float*  sP   = pool;                             // [8][512]

    const int h   = blockIdx.x;
    const int tid = threadIdx.x;
    const int t   = tid & 31;
    const int g   = tid >> 5;

    const float* alh = abslog + h * NN;
    const float* phh = phase  + h * NN;

    // ---- phase A: qtab[n][j] = A^f, f = j (j<8) | 8*(j-8) (8<=j<12) | 32 (j=12)
    #pragma unroll
    for (int k = 0; k < 4; k++) {
        const int e = tid + k * NTHREADS;        // 1024 slots = 64 n x 16
        const int n = e >> 4;
        const int j = e & 15;
        if (j < 13) {
            const float f  = (j < 8) ? (float)j
                           : (j < 12) ? (float)(8 * (j - 8)) : 32.0f;
            const float al = alh[n];
            const float ph = phh[n];
            float2 cs = cis_cw(ph * f);
            float  ex = __expf(al * f);
            qtab[n * QSTRIDE + j] = make_float2(ex * cs.x, ex * cs.y);
        }
    }

    // ---- phase B: W table; 4 anchors per n, recurrence depth 16, step A^64 ----
    {
        const int n  = tid & (NN - 1);
        const int q4 = tid >> 6;                 // quarter in [0,4)
        const float al = alh[n];
        const float ph = phh[n];

        float er = __expf(al);
        float s0, c0;
        __sincosf(ph, &s0, &c0);
        float2 A   = make_float2(er * c0, er * s0);
        float2 Am1 = make_float2(A.x - 1.0f, A.y);
        float2 Cin = make_float2(C[(h * NN + n) * 2], C[(h * NN + n) * 2 + 1]);
        float2 num = cmul(Cin, Am1);
        float  inv = 1.0f / fmaf(al, al, ph * ph);
        float2 Cc;
        Cc.x = 2.0f * (num.x * al + num.y * ph) * inv;
        Cc.y = 2.0f * (num.y * al - num.x * ph) * inv;

        const float e0 = 1024.0f * (float)q4;    // anchor exponent
        float2 P  = cis_cw(ph * e0);
        float  E0 = __expf(al * e0);
        P.x *= E0; P.y *= E0;
        float2 A64 = cis_cw(ph * 64.0f);
        float  E64 = __expf(al * 64.0f);
        A64.x *= E64; A64.y *= E64;

        #pragma unroll
        for (int s = 0; s < 16; s++) {
            sW[16 * q4 + s][n] = cmul(Cc, P);
            P = cmul(P, A64);
        }
    }
    __syncthreads();

    // ---- phase C: register q: q(t) = qhi*qlo ; q(t+32) = q(t)*A^32 ----
    ull qp[NQ], qq[NQ];
    {
        const int jlo = t & 7;
        const int jhi = 8 + (t >> 3);
        #pragma unroll
        for (int i = 0; i < NQ; i++) {
            const int n = g * NQ + i;
            float2 lo  = qtab[n * QSTRIDE + jlo];
            float2 hi  = qtab[n * QSTRIDE + jhi];
            float2 a32 = qtab[n * QSTRIDE + 12];
            float2 q   = cmul(hi, lo);
            float2 q2  = cmul(q, a32);
            qp[i] = pack2(q.x,  -q.y);   // (re, -im): Re(w*conj-form) elementwise
            qq[i] = pack2(q2.x, -q2.y);
        }
    }
    __syncthreads();   // qtab dead; sP aliases it

    // ---- main: 8 sections x (8 tiles x [4 LDS.128 + 16 FFMA2] + reduce) ----
    const ull zero = pack2(0.0f, 0.0f);
    float* sPg = sP + g * LSEC + t;
    float* outh = out + h * LL;

    for (int sec = 0; sec < SECTIONS; sec++) {
        #pragma unroll
        for (int tl2 = 0; tl2 < TPS; tl2++) {
            const int tl = sec * TPS + tl2;
            const ulonglong2* w =
                reinterpret_cast<const ulonglong2*>(&sW[tl][g * NQ]);
            ulonglong2 w0 = w[0], w1 = w[1], w2 = w[2], w3 = w[3];
            ull a0 = zero, a1 = zero, b0 = zero, b1 = zero;
            ffma2(a0, w0.x, qp[0]); ffma2(b0, w0.x, qq[0]);
            ffma2(a1, w0.y, qp[1]); ffma2(b1, w0.y, qq[1]);
            ffma2(a0, w1.x, qp[2]); ffma2(b0, w1.x, qq[2]);
            ffma2(a1, w1.y, qp[3]); ffma2(b1, w1.y, qq[3]);
            ffma2(a0, w2.x, qp[4]); ffma2(b0, w2.x, qq[4]);
            ffma2(a1, w2.y, qp[5]); ffma2(b1, w2.y, qq[5]);
            ffma2(a0, w3.x, qp[6]); ffma2(b0, w3.x, qq[6]);
            ffma2(a1, w3.y, qp[7]); ffma2(b1, w3.y, qq[7]);
            float2 u0 = unpack2(fadd2(a0, a1));
            float2 u1 = unpack2(fadd2(b0, b1));
            sPg[tl2 * 64]      = u0.x + u0.y;
            sPg[tl2 * 64 + 32] = u1.x + u1.y;
        }
        __syncthreads();

        // reduce 8 groups for this 512-l section, coalesced float2 store
        {
            const int j2 = tid * 2;
            float2 acc = *reinterpret_cast<const float2*>(&sP[j2]);
            #pragma unroll
            for (int gg = 1; gg < NGROUPS; gg++) {
                float2 v = *reinterpret_cast<const float2*>(&sP[gg * LSEC + j2]);
                acc.x += v.x; acc.y += v.y;
            }
            *reinterpret_cast<float2*>(&outh[sec * LSEC + j2]) = acc;
        }
        __syncthreads();
    }
}

extern "C" void kernel_launch(void* const* d_in, const int* in_sizes, int n_in,
                              void* d_out, int out_size) {
    const float* abslog = (const float*)d_in[0];  // (H, N) f32
    const float* phase  = (const float*)d_in[1];  // (H, N) f32
    const float* C      = (const float*)d_in[2];  // (1, H, N, 2) f32
    float* out = (float*)d_out;                   // (1, H, L) f32

    ssk_diag_kernel<<<HH, NTHREADS>>>(abslog, phase, C, out);
}

// round 5
// speedup vs baseline: 1.2793x; 1.0020x over previous
#include <cuda_runtime.h>

// SSKernelDiag: out[h,l] = 2 * Re( sum_n Cc[h,n] * A[h,n]^l )
//   A = exp(abslog + i*phase), dtA = abslog + i*phase, Cc = C*(A-1)/dtA
// H=256, N=64, L=4096, CH=1.
//
// R5: grid = H*2 (2048-l chunks) at 4 blocks/SM -> 32 warps/SM (50% occ),
// single wave. 32 KB smem/block (16 KB sW + 16 KB qtab/sP pool).
// Main loop: 32 tiles of 64 l; per tile 4 LDS.128 (broadcast) + 16 FFMA2;
// q(t), q(t+32)=q(t)*A^32 packed in registers.

#define HH 256
#define NN 64
#define LL 4096
#define CHUNKS 2
#define LCHUNK 2048
#define NTILES 32          // tiles of 64 l per chunk
#define SECTIONS 4
#define TPS 8              // tiles per section
#define LSEC 512
#define NTHREADS 256
#define NQ 8               // n per group
#define NGROUPS 8
#define QSTRIDE 16         // qtab row stride (float2)

typedef unsigned long long ull;

__device__ __forceinline__ float2 cmul(float2 a, float2 b) {
    return make_float2(fmaf(a.x, b.x, -(a.y * b.y)),
                       fmaf(a.x, b.y,  (a.y * b.x)));
}

// exp(i*y), 2-term Cody-Waite reduction; accurate for |y| <~ 2^14.
__device__ __forceinline__ float2 cis_cw(float y) {
    float m = rintf(y * 0.15915494309189535f);
    float r = fmaf(m, -6.28125f, y);          // 2*pi hi (exact in fp32)
    r = fmaf(m, -1.9353072e-3f, r);           // 2*pi lo
    float s, c;
    __sincosf(r, &s, &c);
    return make_float2(c, s);
}

__device__ __forceinline__ ull pack2(float x, float y) {
    ull r;
    asm("mov.b64 %0, {%1, %2};" : "=l"(r) : "f"(x), "f"(y));
    return r;
}
__device__ __forceinline__ float2 unpack2(ull v) {
    float x, y;
    asm("mov.b64 {%0, %1}, %2;" : "=f"(x), "=f"(y) : "l"(v));
    return make_float2(x, y);
}
__device__ __forceinline__ void ffma2(ull& acc, ull a, ull b) {
    asm("fma.rn.f32x2 %0, %1, %2, %0;" : "+l"(acc) : "l"(a), "l"(b));
}
__device__ __forceinline__ ull fadd2(ull a, ull b) {
    ull r;
    asm("add.rn.f32x2 %0, %1, %2;" : "=l"(r) : "l"(a), "l"(b));
    return r;
}

__global__ void __launch_bounds__(NTHREADS, 4)
ssk_diag_kernel(const float* __restrict__ abslog,
                const float* __restrict__ phase,
                const float* __restrict__ C,
                float* __restrict__ out) {
    __shared__ float2 sW[NTILES][NN];            // 16 KB: W[tl][n], step A^64
    __shared__ float  pool[NGROUPS * LSEC];      // 16 KB: qtab / sP
    float2* qtab = reinterpret_cast<float2*>(pool);  // [64][16] (8 KB used)
    float*  sP   = pool;                             // [8][512]

    const int bid   = blockIdx.x;
    const int h     = bid >> 1;
    const int chunk = bid & 1;
    const int tid   = threadIdx.x;
    const int t     = tid & 31;
    const int g     = tid >> 5;

    const float* alh = abslog + h * NN;
    const float* phh = phase  + h * NN;
    const float  l0f = (float)(chunk * LCHUNK);

    // ---- phase A: qtab[n][j] = A^f, f = j (j<8) | 8*(j-8) (8<=j<12) | 32 (j=12)
    #pragma unroll
    for (int k = 0; k < 4; k++) {
        const int e = tid + k * NTHREADS;        // 1024 slots = 64 n x 16
        const int n = e >> 4;
        const int j = e & 15;
        if (j < 13) {
            const float f  = (j < 8) ? (float)j
                           : (j < 12) ? (float)(8 * (j - 8)) : 32.0f;
            const float al = alh[n];
            const float ph = phh[n];
            float2 cs = cis_cw(ph * f);
            float  ex = __expf(al * f);
            qtab[n * QSTRIDE + j] = make_float2(ex * cs.x, ex * cs.y);
        }
    }

    // ---- phase B: W table; 4 anchors per n, recurrence depth 8, step A^64 ----
    {
        const int n  = tid & (NN - 1);
        const int q4 = tid >> 6;                 // quarter in [0,4)
        const float al = alh[n];
        const float ph = phh[n];

        float er = __expf(al);
        float s0, c0;
        __sincosf(ph, &s0, &c0);
        float2 A   = make_float2(er * c0, er * s0);
        float2 Am1 = make_float2(A.x - 1.0f, A.y);
        float2 Cin = make_float2(C[(h * NN + n) * 2], C[(h * NN + n) * 2 + 1]);
        float2 num = cmul(Cin, Am1);
        float  inv = 1.0f / fmaf(al, al, ph * ph);
        float2 Cc;
        Cc.x = 2.0f * (num.x * al + num.y * ph) * inv;
        Cc.y = 2.0f * (num.y * al - num.x * ph) * inv;

        const float e0 = l0f + 512.0f * (float)q4;   // anchor exponent
        float2 P  = cis_cw(ph * e0);
        float  E0 = __expf(al * e0);
        P.x *= E0; P.y *= E0;
        float2 A64 = cis_cw(ph * 64.0f);
        float  E64 = __expf(al * 64.0f);
        A64.x *= E64; A64.y *= E64;

        #pragma unroll
        for (int s = 0; s < 8; s++) {
            sW[8 * q4 + s][n] = cmul(Cc, P);
            P = cmul(P, A64);
        }
    }
    __syncthreads();

    // ---- phase C: register q: q(t) = qhi*qlo ; q(t+32) = q(t)*A^32 ----
    ull qp[NQ], qq[NQ];
    {
        const int jlo = t & 7;
        const int jhi = 8 + (t >> 3);
        #pragma unroll
        for (int i = 0; i < NQ; i++) {
            const int n = g * NQ + i;
            float2 lo  = qtab[n * QSTRIDE + jlo];
            float2 hi  = qtab[n * QSTRIDE + jhi];
            float2 a32 = qtab[n * QSTRIDE + 12];
            float2 q   = cmul(hi, lo);
            float2 q2  = cmul(q, a32);
            qp[i] = pack2(q.x,  -q.y);   // (re, -im) so Re(w*q) = dot elementwise
            qq[i] = pack2(q2.x, -q2.y);
        }
    }
    __syncthreads();   // qtab dead; sP aliases it

    // ---- main: 4 sections x (8 tiles x [4 LDS.128 + 16 FFMA2] + reduce) ----
    const ull zero = pack2(0.0f, 0.0f);
    float* sPg = sP + g * LSEC + t;
    float* outh = out + h * LL + chunk * LCHUNK;

    for (int sec = 0; sec < SECTIONS; sec++) {
        #pragma unroll
        for (int tl2 = 0; tl2 < TPS; tl2++) {
            const int tl = sec * TPS + tl2;
            const ulonglong2* w =
                reinterpret_cast<const ulonglong2*>(&sW[tl][g * NQ]);
            ulonglong2 w0 = w[0], w1 = w[1], w2 = w[2], w3 = w[3];
            ull a0 = zero, a1 = zero, b0 = zero, b1 = zero;
            ffma2(a0, w0.x, qp[0]); ffma2(b0, w0.x, qq[0]);
            ffma2(a1, w0.y, qp[1]); ffma2(b1, w0.y, qq[1]);
            ffma2(a0, w1.x, qp[2]); ffma2(b0, w1.x, qq[2]);
            ffma2(a1, w1.y, qp[3]); ffma2(b1, w1.y, qq[3]);
            ffma2(a0, w2.x, qp[4]); ffma2(b0, w2.x, qq[4]);
            ffma2(a1, w2.y, qp[5]); ffma2(b1, w2.y, qq[5]);
            ffma2(a0, w3.x, qp[6]); ffma2(b0, w3.x, qq[6]);
            ffma2(a1, w3.y, qp[7]); ffma2(b1, w3.y, qq[7]);
            float2 u0 = unpack2(fadd2(a0, a1));
            float2 u1 = unpack2(fadd2(b0, b1));
            sPg[tl2 * 64]      = u0.x + u0.y;
            sPg[tl2 * 64 + 32] = u1.x + u1.y;
        }
        __syncthreads();

        // reduce 8 groups for this 512-l section, coalesced float2 store
        {
            const int j2 = tid * 2;
            float2 acc = *reinterpret_cast<const float2*>(&sP[j2]);
            #pragma unroll
            for (int gg = 1; gg < NGROUPS; gg++) {
                float2 v = *reinterpret_cast<const float2*>(&sP[gg * LSEC + j2]);
                acc.x += v.x; acc.y += v.y;
            }
            *reinterpret_cast<float2*>(&outh[sec * LSEC + j2]) = acc;
        }
        __syncthreads();
    }
}

extern "C" void kernel_launch(void* const* d_in, const int* in_sizes, int n_in,
                              void* d_out, int out_size) {
    const float* abslog = (const float*)d_in[0];  // (H, N) f32
    const float* phase  = (const float*)d_in[1];  // (H, N) f32
    const float* C      = (const float*)d_in[2];  // (1, H, N, 2) f32
    float* out = (float*)d_out;                   // (1, H, L) f32

    ssk_diag_kernel<<<HH * CHUNKS, NTHREADS>>>(abslog, phase, C, out);
}

// round 6
// speedup vs baseline: 1.3589x; 1.0622x over previous
#include <cuda_runtime.h>

// SSKernelDiag: out[h,l] = 2 * Re( sum_n Cc[h,n] * A[h,n]^l )
//   A = exp(abslog + i*phase), dtA = abslog + i*phase, Cc = C*(A-1)/dtA
// H=256, N=64, L=4096, CH=1.
//
// R6: minimize issue count so the FFMA2 pipe (rt=3 due to 64-bit operand
// banking) becomes the binding roofline. One block per head, 512 threads.
// Thread (t in [0,32), g in [0,16)) owns 4 n and 4 CONSECUTIVE l
// (l = 128*tile + 4t + k). Per 128-l tile: 2 LDS.128 + 16 FFMA2 (4 indep
// chains) + 1 STS.128. Output staged in 8 sections of 512 l.

#define HH 256
#define NN 64
#define LL 4096
#define NTILES 32          // tiles of 128 l
#define SECTIONS 8
#define TPS 4              // tiles per section
#define LSEC 512
#define NTHREADS 512
#define NQ 4               // n per group
#define NGROUPS 16
#define QSTRIDE 16         // qtab row stride (float2)

typedef unsigned long long ull;

__device__ __forceinline__ float2 cmul(float2 a, float2 b) {
    return make_float2(fmaf(a.x, b.x, -(a.y * b.y)),
                       fmaf(a.x, b.y,  (a.y * b.x)));
}

// exp(i*y), 2-term Cody-Waite reduction; accurate for |y| <~ 2^14.
__device__ __forceinline__ float2 cis_cw(float y) {
    float m = rintf(y * 0.15915494309189535f);
    float r = fmaf(m, -6.28125f, y);          // 2*pi hi (exact in fp32)
    r = fmaf(m, -1.9353072e-3f, r);           // 2*pi lo
    float s, c;
    __sincosf(r, &s, &c);
    return make_float2(c, s);
}

__device__ __forceinline__ ull pack2(float x, float y) {
    ull r;
    asm("mov.b64 %0, {%1, %2};" : "=l"(r) : "f"(x), "f"(y));
    return r;
}
__device__ __forceinline__ float2 unpack2(ull v) {
    float x, y;
    asm("mov.b64 {%0, %1}, %2;" : "=f"(x), "=f"(y) : "l"(v));
    return make_float2(x, y);
}
__device__ __forceinline__ void ffma2(ull& acc, ull a, ull b) {
    asm("fma.rn.f32x2 %0, %1, %2, %0;" : "+l"(acc) : "l"(a), "l"(b));
}
__device__ __forceinline__ ull fadd2(ull a, ull b) {
    ull r;
    asm("add.rn.f32x2 %0, %1, %2;" : "=l"(r) : "l"(a), "l"(b));
    return r;
}

__global__ void __launch_bounds__(NTHREADS, 2)
ssk_diag_kernel(const float* __restrict__ abslog,
                const float* __restrict__ phase,
                const float* __restrict__ C,
                float* __restrict__ out) {
    __shared__ float2 sW[NTILES][NN];            // 16 KB: W[tl][n], step A^128
    __shared__ float  pool[NGROUPS * LSEC];      // 32 KB: qtab / sP
    float2* qtab = reinterpret_cast<float2*>(pool);  // [64][16] (8 KB used)
    float*  sP   = pool;                             // [16][512]

    const int h   = blockIdx.x;
    const int tid = threadIdx.x;
    const int t   = tid & 31;
    const int g   = tid >> 5;        // n-group in [0,16)

    const float* alh = abslog + h * NN;
    const float* phh = phase  + h * NN;

    // ---- phase A: qtab[n][j]:
    //   j in [0,8):  A^(4j)      (low part of A^(4t))
    //   j in [8,12): A^(32(j-8)) (high part)
    //   j in [12,15): A^(j-11)   (A^1, A^2, A^3 for the 4-point offsets)
    #pragma unroll
    for (int k = 0; k < 2; k++) {
        const int e = tid + k * NTHREADS;        // 64 n x 16 slots
        const int n = e >> 4;
        const int j = e & 15;
        if (e < NN * 16 && j < 15) {
            const float f = (j < 8)  ? (float)(4 * j)
                          : (j < 12) ? (float)(32 * (j - 8))
                                     : (float)(j - 11);
            const float al = alh[n];
            const float ph = phh[n];
            float2 cs = cis_cw(ph * f);
            float  ex = __expf(al * f);
            qtab[n * QSTRIDE + j] = make_float2(ex * cs.x, ex * cs.y);
        }
    }

    // ---- phase B: W table; 8 anchors per n, recurrence depth 4, step A^128 ----
    {
        const int n   = tid & (NN - 1);
        const int oct = tid >> 6;                // [0,8)
        const float al = alh[n];
        const float ph = phh[n];

        float er = __expf(al);
        float s0, c0;
        __sincosf(ph, &s0, &c0);
        float2 A   = make_float2(er * c0, er * s0);
        float2 Am1 = make_float2(A.x - 1.0f, A.y);
        float2 Cin = reinterpret_cast<const float2*>(C)[h * NN + n];
        float2 num = cmul(Cin, Am1);
        float  inv = 1.0f / fmaf(al, al, ph * ph);
        float2 Cc;
        Cc.x = 2.0f * (num.x * al + num.y * ph) * inv;
        Cc.y = 2.0f * (num.y * al - num.x * ph) * inv;

        const float e0 = 512.0f * (float)oct;    // anchor exponent
        float2 P  = cis_cw(ph * e0);
        float  E0 = __expf(al * e0);
        P.x *= E0; P.y *= E0;
        float2 A128 = cis_cw(ph * 128.0f);
        float  E128 = __expf(al * 128.0f);
        A128.x *= E128; A128.y *= E128;

        #pragma unroll
        for (int s = 0; s < 4; s++) {
            sW[4 * oct + s][n] = cmul(Cc, P);
            P = cmul(P, A128);
        }
    }
    __syncthreads();

    // ---- phase C: register q: qp[k][i] = conj-packed A_n^(4t+k), n=g*4+i ----
    ull qp[4][NQ];
    {
        const int jlo = t & 7;
        const int jhi = 8 + (t >> 3);
        #pragma unroll
        for (int i = 0; i < NQ; i++) {
            const int n = g * NQ + i;
            float2 lo = qtab[n * QSTRIDE + jlo];
            float2 hi = qtab[n * QSTRIDE + jhi];
            float2 a1 = qtab[n * QSTRIDE + 12];
            float2 a2 = qtab[n * QSTRIDE + 13];
            float2 a3 = qtab[n * QSTRIDE + 14];
            float2 q0 = cmul(hi, lo);            // A^(4t)
            float2 q1 = cmul(q0, a1);
            float2 q2 = cmul(q0, a2);
            float2 q3 = cmul(q0, a3);
            qp[0][i] = pack2(q0.x, -q0.y);
            qp[1][i] = pack2(q1.x, -q1.y);
            qp[2][i] = pack2(q2.x, -q2.y);
            qp[3][i] = pack2(q3.x, -q3.y);
        }
    }
    __syncthreads();   // qtab dead; sP aliases it

    // ---- main: 8 sections x (4 tiles x [2 LDS.128 + 16 FFMA2 + STS.128]) ----
    const ull zero = pack2(0.0f, 0.0f);
    float* sPg  = sP + g * LSEC + 4 * t;
    float* outh = out + h * LL;

    for (int sec = 0; sec < SECTIONS; sec++) {
        #pragma unroll
        for (int ts = 0; ts < TPS; ts++) {
            const int tl = sec * TPS + ts;
            const ulonglong2* w =
                reinterpret_cast<const ulonglong2*>(&sW[tl][g * NQ]);
            ulonglong2 w0 = w[0], w1 = w[1];     // 4 complex W
            ull a0 = zero, a1 = zero, a2 = zero, a3 = zero;
            ffma2(a0, w0.x, qp[0][0]); ffma2(a1, w0.x, qp[1][0]);
            ffma2(a2, w0.x, qp[2][0]); ffma2(a3, w0.x, qp[3][0]);
            ffma2(a0, w0.y, qp[0][1]); ffma2(a1, w0.y, qp[1][1]);
            ffma2(a2, w0.y, qp[2][1]); ffma2(a3, w0.y, qp[3][1]);
            ffma2(a0, w1.x, qp[0][2]); ffma2(a1, w1.x, qp[1][2]);
            ffma2(a2, w1.x, qp[2][2]); ffma2(a3, w1.x, qp[3][2]);
            ffma2(a0, w1.y, qp[0][3]); ffma2(a1, w1.y, qp[1][3]);
            ffma2(a2, w1.y, qp[2][3]); ffma2(a3, w1.y, qp[3][3]);
            float2 u0 = unpack2(a0), u1 = unpack2(a1);
            float2 u2 = unpack2(a2), u3 = unpack2(a3);
            float4 r;
            r.x = u0.x + u0.y; r.y = u1.x + u1.y;
            r.z = u2.x + u2.y; r.w = u3.x + u3.y;
            *reinterpret_cast<float4*>(&sPg[ts * 128]) = r;
        }
        __syncthreads();

        // reduce 16 groups for this 512-l section (threads 0..127, float4)
        if (tid < 128) {
            const ulonglong2* p = reinterpret_cast<const ulonglong2*>(sP) + tid;
            ulonglong2 acc = p[0];
            #pragma unroll
            for (int gg = 1; gg < NGROUPS; gg++) {
                ulonglong2 v = p[gg * (LSEC / 4)];
                acc.x = fadd2(acc.x, v.x);
                acc.y = fadd2(acc.y, v.y);
            }
            reinterpret_cast<ulonglong2*>(&outh[sec * LSEC])[tid] = acc;
        }
        __syncthreads();
    }
}

extern "C" void kernel_launch(void* const* d_in, const int* in_sizes, int n_in,
                              void* d_out, int out_size) {
    const float* abslog = (const float*)d_in[0];  // (H, N) f32
    const float* phase  = (const float*)d_in[1];  // (H, N) f32
    const float* C      = (const float*)d_in[2];  // (1, H, N, 2) f32
    float* out = (float*)d_out;                   // (1, H, L) f32

    ssk_diag_kernel<<<HH, NTHREADS>>>(abslog, phase, C, out);
}